// round 16
// baseline (speedup 1.0000x reference)
#include <cuda_runtime.h>

// ComplexityAnalyzer: per-image 64-bin histogram + L1 normalize + 64->32->128 MLP.
// Inputs: grad_map [B*512*512] f32, W1 [32*64], b1 [32], W2 [128*32], b2 [128].
// Output: [B*128] f32.
//
// R16: the shared-ATOMS unit (~5 lane-ops/cyc/SM, conflict-independent) is the
// proven wall; it scales only with active SMs. 148 CTAs x 512 threads (1/SM,
// NO 64-reg cap -> ~90 regs) so ptxas keeps a depth-4 LDG.128 pipeline live
// alongside the 2-bank boundary state that 1024-thread variants couldn't
// afford. Flat split in 512-float4 iters; per-image completion via global
// hist + done counter; finishing CTA runs the MLP and self-cleans scratch.

#define THREADS 512
#define WARPS   16
#define NPAD    66            // 64 bins + padding words
#define HBANK   (WARPS * NPAD)
#define IT_F4   512           // float4 per CTA-iteration (1 per thread)
#define IPI     128           // iterations per image (65536/512)
#define MAX_IMG 256

__device__ unsigned int g_hist[MAX_IMG * 64];   // zero-init; self-cleaning
__device__ unsigned int g_done[MAX_IMG];        // zero-init; self-cleaning

__global__ __launch_bounds__(THREADS, 1)
void ca_hist_mlp_kernel(const float* __restrict__ grad,
                        const float* __restrict__ W1, const float* __restrict__ b1,
                        const float* __restrict__ W2, const float* __restrict__ b2,
                        float* __restrict__ out, int totalIters)
{
    __shared__ unsigned int hist[2 * HBANK];    // bank A (imgA) + bank B (imgB)
    __shared__ float fh[64];
    __shared__ float hmid[32];
    __shared__ float inv_s;
    __shared__ int sh_doA, sh_doB;

    const int tid = threadIdx.x;
    const int wid = tid >> 5;

    // Flat contiguous split in iteration units.
    const int nCta = gridDim.x;
    const int base = totalIters / nCta;
    const int rem  = totalIters % nCta;
    const int s    = blockIdx.x * base + min((int)blockIdx.x, rem);
    const int n    = base + ((int)blockIdx.x < rem ? 1 : 0);

    const int imgA = s / IPI;
    const int nA   = min(n, (imgA + 1) * IPI - s);   // iters in imgA
    const int nB   = n - nA;
    const int imgB = imgA + 1;

    #pragma unroll
    for (int i = tid; i < 2 * HBANK; i += THREADS)
        hist[i] = 0u;
    __syncthreads();

    unsigned int* hA = hist + wid * NPAD;
    unsigned int* hB = hA + HBANK;
    const float4* p = (const float4*)grad + (size_t)s * IT_F4 + tid;

    const float scale = 64.0f / 255.0f;
    const float magic = 8388608.0f;  // 2^23

    // bin = low mantissa of fma.rz(v, 64/255, 2^23), strictly in [0,63]
    #define PROC(h, v)                                                             \
        do {                                                                       \
            float q0, q1, q2, q3;                                                  \
            asm("fma.rz.f32 %0, %1, %2, %3;" : "=f"(q0) : "f"((v).x), "f"(scale), "f"(magic)); \
            asm("fma.rz.f32 %0, %1, %2, %3;" : "=f"(q1) : "f"((v).y), "f"(scale), "f"(magic)); \
            asm("fma.rz.f32 %0, %1, %2, %3;" : "=f"(q2) : "f"((v).z), "f"(scale), "f"(magic)); \
            asm("fma.rz.f32 %0, %1, %2, %3;" : "=f"(q3) : "f"((v).w), "f"(scale), "f"(magic)); \
            atomicAdd(&(h)[__float_as_uint(q0) & 0x3Fu], 1u);                      \
            atomicAdd(&(h)[__float_as_uint(q1) & 0x3Fu], 1u);                      \
            atomicAdd(&(h)[__float_as_uint(q2) & 0x3Fu], 1u);                      \
            atomicAdd(&(h)[__float_as_uint(q3) & 0x3Fu], 1u);                      \
        } while (0)

    // Depth-4 software pipeline over n iters (n >= 8 always for this problem).
    const int n4 = (n - 4) & ~3;        // main-loop trip (multiple of 4)
    float4 v0 = __ldg(&p[0 * IT_F4]);
    float4 v1 = __ldg(&p[1 * IT_F4]);
    float4 v2 = __ldg(&p[2 * IT_F4]);
    float4 v3 = __ldg(&p[3 * IT_F4]);
    int it = 0;
    #pragma unroll 1
    for (; it < n4; it += 4) {
        float4 w0 = __ldg(&p[(it + 4) * IT_F4]);
        float4 w1 = __ldg(&p[(it + 5) * IT_F4]);
        float4 w2 = __ldg(&p[(it + 6) * IT_F4]);
        float4 w3 = __ldg(&p[(it + 7) * IT_F4]);
        { unsigned int* h = (it + 0 >= nA) ? hB : hA; PROC(h, v0); }
        { unsigned int* h = (it + 1 >= nA) ? hB : hA; PROC(h, v1); }
        { unsigned int* h = (it + 2 >= nA) ? hB : hA; PROC(h, v2); }
        { unsigned int* h = (it + 3 >= nA) ? hB : hA; PROC(h, v3); }
        v0 = w0; v1 = w1; v2 = w2; v3 = w3;
    }
    // Drain the 4 prefetched iters
    { unsigned int* h = (it + 0 >= nA) ? hB : hA; PROC(h, v0); }
    { unsigned int* h = (it + 1 >= nA) ? hB : hA; PROC(h, v1); }
    { unsigned int* h = (it + 2 >= nA) ? hB : hA; PROC(h, v2); }
    { unsigned int* h = (it + 3 >= nA) ? hB : hA; PROC(h, v3); }
    it += 4;
    // Remainder (0..3 iters)
    for (; it < n; ++it) {
        float4 v = __ldg(&p[it * IT_F4]);
        unsigned int* h = (it >= nA) ? hB : hA;
        PROC(h, v);
    }
    __syncthreads();

    // Flush both banks in parallel: tid 0-63 bank A, 64-127 bank B.
    if (tid < 128) {
        const int bankB = tid >> 6;
        const int bin   = tid & 63;
        if (!bankB || nB > 0) {
            const unsigned int* hb = hist + bankB * HBANK;
            unsigned t = 0;
            #pragma unroll
            for (int w = 0; w < WARPS; ++w)
                t += hb[w * NPAD + bin];
            const int im = bankB ? imgB : imgA;
            if (t) atomicAdd(&g_hist[im * 64 + bin], t);
        }
        __threadfence();                       // release before done-count
    }
    __syncthreads();

    if (tid == 0) {
        unsigned old = atomicAdd(&g_done[imgA], (unsigned)nA);
        sh_doA = (old + (unsigned)nA == (unsigned)IPI);
    }
    if (tid == 1) {
        int d = 0;
        if (nB > 0) {
            unsigned old = atomicAdd(&g_done[imgB], (unsigned)nB);
            d = (old + (unsigned)nB == (unsigned)IPI);
        }
        sh_doB = d;
    }
    __syncthreads();

    #pragma unroll 1
    for (int pass = 0; pass < 2; ++pass) {
        const int run = pass ? sh_doB : sh_doA;
        const int img = pass ? imgB : imgA;
        if (!run) continue;
        if (tid < 64) {
            __threadfence();                    // acquire
            fh[tid] = (float)atomicAdd(&g_hist[img * 64 + tid], 0u);
        }
        __syncthreads();
        if (tid < 32) {
            float t = fh[tid] + fh[tid + 32];
            #pragma unroll
            for (int off = 16; off > 0; off >>= 1)
                t += __shfl_down_sync(0xFFFFFFFFu, t, off);
            if (tid == 0) inv_s = 1.0f / fmaxf(t, 1e-12f);
        }
        __syncthreads();
        if (tid < 64) fh[tid] *= inv_s;
        __syncthreads();
        if (tid < 32) {
            float acc = b1[tid];
            const float* w = W1 + tid * 64;
            #pragma unroll
            for (int b = 0; b < 64; ++b) acc = fmaf(fh[b], w[b], acc);
            hmid[tid] = fmaxf(acc, 0.0f);
        }
        __syncthreads();
        if (tid < 128) {
            float acc = b2[tid];
            const float* w = W2 + tid * 32;
            #pragma unroll
            for (int j = 0; j < 32; ++j) acc = fmaf(hmid[j], w[j], acc);
            out[img * 128 + tid] = acc;
        }
        // self-clean scratch for deterministic graph replays
        if (tid < 64) atomicExch(&g_hist[img * 64 + tid], 0u);
        if (tid == 0) atomicExch(&g_done[img], 0u);
        __syncthreads();
    }
}

extern "C" void kernel_launch(void* const* d_in, const int* in_sizes, int n_in,
                              void* d_out, int out_size) {
    const float* grad = (const float*)d_in[0];
    const float* W1   = (const float*)d_in[1];
    const float* b1   = (const float*)d_in[2];
    const float* W2   = (const float*)d_in[3];
    const float* b2   = (const float*)d_in[4];
    float* out = (float*)d_out;

    int totalIters = in_sizes[0] / (4 * IT_F4);
    int nCta = totalIters < 148 ? totalIters : 148;
    ca_hist_mlp_kernel<<<nCta, THREADS>>>(grad, W1, b1, W2, b2, out, totalIters);
}